// round 12
// baseline (speedup 1.0000x reference)
#include <cuda_runtime.h>
#include <cuda_fp16.h>
#include <cstdint>

#define B_TOTAL  8192
#define T_STEPS  512
#define HID      128
#define BM       64      // rows per CTA: 4 row-groups x 16
#define NTHREADS 256     // 8 warps = 4 row-groups x 2 n-halves
#define NKT      9       // k-tiles: 128 h + [x0,x1,bias] tile
#define NNT      16      // n-tiles total (8 per warp)
#define ALPHA_C  0.2f
#define BETA_C   0.7f

#define SB_U4     (NKT * NNT * 32)     // 4608 uint4 B fragments
#define SB_BYTES  (SB_U4 * 16)         // 73728
#define SX_BYTES  (2 * 8 * 512 * 4)    // 32768: double-buffered h exchange

__device__ __forceinline__ float tanh_hw(float x) {
    float y; asm("tanh.approx.f32 %0, %1;" : "=f"(y) : "f"(x)); return y;
}
__device__ __forceinline__ uint32_t f16x2(float lo, float hi) {
    uint32_t r; asm("cvt.rn.f16x2.f32 %0, %1, %2;" : "=r"(r) : "f"(hi), "f"(lo));
    return r;
}
__device__ __forceinline__ void mma16816(float c[4], const uint32_t a[4],
                                         uint32_t b0, uint32_t b1) {
    asm("mma.sync.aligned.m16n8k16.row.col.f32.f16.f16.f32 "
        "{%0,%1,%2,%3}, {%4,%5,%6,%7}, {%8,%9}, {%0,%1,%2,%3};"
        : "+f"(c[0]), "+f"(c[1]), "+f"(c[2]), "+f"(c[3])
        : "r"(a[0]), "r"(a[1]), "r"(a[2]), "r"(a[3]), "r"(b0), "r"(b1));
}

extern __shared__ char smem[];

__global__ __launch_bounds__(NTHREADS, 1)
void rnn_kernel(const float* __restrict__ input,   // (B, T, 2)
                const float* __restrict__ W_rec,   // (130, 128)
                const float* __restrict__ b_rec,   // (128)
                const float* __restrict__ W_out,   // (128, 1)
                const float* __restrict__ b_out,   // (1)
                float* __restrict__ out)           // (B)
{
    uint4*    sB  = (uint4*)smem;                             // [nt][kt][lane]
    uint32_t* sX  = (uint32_t*)(smem + SB_BYTES);             // h exchange
    float2*   sWP = (float2*)(smem + SB_BYTES + SX_BYTES);    // [nt][tig]
    float*    sRed = (float*)(smem + SB_BYTES + SX_BYTES + NNT * 4 * 8);

    const int tid  = threadIdx.x;
    const int lane = tid & 31;
    const int wid  = tid >> 5;
    const int tig  = lane & 3;     // col group within fragment
    const int gid  = lane >> 2;    // row group 0..7
    const int half = wid >> 2;     // n-half: 0 -> nt 0..7, 1 -> nt 8..15
    const int wrow = wid & 3;      // row-group id
    const int ktb  = half * 4;     // own h k-tiles
    const int ktbp = (half ^ 1) * 4;
    const int ntb  = half * 8;
    const int bBase = blockIdx.x * BM;

    // ---- build B fragments: W'(k,n) split into f16 hi + residual, fused uint4
    for (int idx = tid; idx < NKT * NNT * 32; idx += NTHREADS) {
        int l  = idx & 31;
        int kt = (idx >> 5) % NKT;
        int nt = (idx >> 5) / NKT;
        int n  = nt * 8 + (l >> 2);
        int kb = kt * 16 + 2 * (l & 3);
        unsigned short h0q[4], h1q[4];
        #pragma unroll
        for (int q = 0; q < 4; q++) {
            int k = kb + (q >> 1) * 8 + (q & 1);
            float v;
            if      (k < 128)  v = W_rec[(k + 2) * HID + n];
            else if (k == 128) v = W_rec[n];
            else if (k == 129) v = W_rec[HID + n];
            else if (k == 130) v = b_rec[n];
            else               v = 0.0f;
            __half vh = __float2half_rn(v);
            __half vl = __float2half_rn(v - __half2float(vh));
            h0q[q] = __half_as_ushort(vh);
            h1q[q] = __half_as_ushort(vl);
        }
        uint4 bv;
        bv.x = (uint32_t)h0q[0] | ((uint32_t)h0q[1] << 16);
        bv.y = (uint32_t)h0q[2] | ((uint32_t)h0q[3] << 16);
        bv.z = (uint32_t)h1q[0] | ((uint32_t)h1q[1] << 16);
        bv.w = (uint32_t)h1q[2] | ((uint32_t)h1q[3] << 16);
        sB[(nt * NKT + kt) * 32 + l] = bv;
    }
    if (tid < NNT * 4) {
        int nt = tid >> 2, c = tid & 3;
        sWP[tid] = make_float2(W_out[nt * 8 + 2 * c], W_out[nt * 8 + 2 * c + 1]);
    }
    __syncthreads();

    // ---- per-thread recurrent state (rows shared by the warp pair) ----
    const int r0 = wrow * 16 + gid;
    const int r8 = r0 + 8;
    const long long off0 = (long long)(bBase + r0) * (T_STEPS * 2);
    const long long off8 = (long long)(bBase + r8) * (T_STEPS * 2);
    const float bout = b_out[0];

    float2 x0c = *(const float2*)(input + off0);
    float2 x8c = *(const float2*)(input + off8);
    float racc0 = 0.f, racc8 = 0.f, prev0 = 0.f, prev8 = 0.f;
    float oacc0 = 0.f, oacc8 = 0.f;

    const uint32_t ONEH = 0x00003C00u;   // {lo=1.0h (bias slot), hi=0}

    uint32_t a[NKT][4];
    #pragma unroll
    for (int kt = 0; kt < 8; kt++)
        #pragma unroll
        for (int q = 0; q < 4; q++) a[kt][q] = 0u;   // h_{-1} = 0
    a[8][0] = (tig == 0) ? f16x2(x0c.x, x0c.y) : (tig == 1) ? ONEH : 0u;
    a[8][1] = (tig == 0) ? f16x2(x8c.x, x8c.y) : (tig == 1) ? ONEH : 0u;
    a[8][2] = 0u; a[8][3] = 0u;

    for (int t = 0; t < T_STEPS; ++t) {
        float2 x0n = make_float2(0.f, 0.f), x8n = make_float2(0.f, 0.f);
        if (t + 1 < T_STEPS) {
            x0n = *(const float2*)(input + off0 + (long long)(t + 1) * 2);
            x8n = *(const float2*)(input + off8 + (long long)(t + 1) * 2);
        }

        // ---- GEMM over own n-half: kt-outer, independent c-tiles inner ----
        float c[8][4];
        #pragma unroll
        for (int ntl = 0; ntl < 8; ntl++) {
            c[ntl][0] = 0.f; c[ntl][1] = 0.f; c[ntl][2] = 0.f; c[ntl][3] = 0.f;
        }
        #pragma unroll
        for (int kt = 0; kt < NKT; kt++) {
            uint4 bv[8];
            const uint4* bp = sB + (ntb * NKT + kt) * 32 + lane;
            #pragma unroll
            for (int ntl = 0; ntl < 8; ntl++) bv[ntl] = bp[ntl * (NKT * 32)];
            #pragma unroll
            for (int ntl = 0; ntl < 8; ntl++)
                mma16816(c[ntl], a[kt], bv[ntl].x, bv[ntl].y);   // W hi
            #pragma unroll
            for (int ntl = 0; ntl < 8; ntl++)
                mma16816(c[ntl], a[kt], bv[ntl].z, bv[ntl].w);   // W residual
        }

        // ---- tanh + omega partials + own A fragments ----
        float pr0 = 0.f, pr8 = 0.f;
        #pragma unroll
        for (int ntl = 0; ntl < 8; ntl++) {
            float t0 = tanh_hw(c[ntl][0]);
            float t1 = tanh_hw(c[ntl][1]);
            float t2 = tanh_hw(c[ntl][2]);
            float t3 = tanh_hw(c[ntl][3]);
            float2 wp = sWP[(ntb + ntl) * 4 + tig];
            pr0 += t0 * wp.x + t1 * wp.y;
            pr8 += t2 * wp.x + t3 * wp.y;
            const int ko = ktb + (ntl >> 1), hh = (ntl & 1) << 1;
            a[ko][hh]     = f16x2(t0, t1);
            a[ko][hh + 1] = f16x2(t2, t3);
        }

        // ---- exchange own 4 k-tiles with partner warp (wid^4) ----
        uint32_t* xw = sX + (t & 1) * 4096 + wid * 512;
        #pragma unroll
        for (int g = 0; g < 4; g++)
            *(uint4*)(xw + g * 128 + lane * 4) =
                make_uint4(a[ktb + g][0], a[ktb + g][1], a[ktb + g][2], a[ktb + g][3]);
        __syncthreads();
        const uint32_t* xr = sX + (t & 1) * 4096 + (wid ^ 4) * 512;
        #pragma unroll
        for (int g = 0; g < 4; g++) {
            uint4 v = *(const uint4*)(xr + g * 128 + lane * 4);
            a[ktbp + g][0] = v.x; a[ktbp + g][1] = v.y;
            a[ktbp + g][2] = v.z; a[ktbp + g][3] = v.w;
        }

        // ---- scalar recursions + x tile ----
        oacc0 = oacc0 * BETA_C + pr0;
        oacc8 = oacc8 * BETA_C + pr8;
        racc0 = racc0 * BETA_C + prev0 * prev0;  prev0 = x0c.x;
        racc8 = racc8 * BETA_C + prev8 * prev8;  prev8 = x8c.x;
        a[8][0] = (tig == 0) ? f16x2(x0n.x, x0n.y) : (tig == 1) ? ONEH : 0u;
        a[8][1] = (tig == 0) ? f16x2(x8n.x, x8n.y) : (tig == 1) ? ONEH : 0u;
        x0c = x0n; x8c = x8n;
    }

    // ---- final: reduce omega over tig lanes, then over the two n-halves ----
    oacc0 += __shfl_xor_sync(0xffffffffu, oacc0, 1);
    oacc0 += __shfl_xor_sync(0xffffffffu, oacc0, 2);
    oacc8 += __shfl_xor_sync(0xffffffffu, oacc8, 1);
    oacc8 += __shfl_xor_sync(0xffffffffu, oacc8, 2);

    if (tig == 0) {
        sRed[half * 64 + wrow * 16 + gid]     = oacc0;
        sRed[half * 64 + wrow * 16 + gid + 8] = oacc8;
    }
    __syncthreads();
    if (half == 0 && tig == 0) {
        float om0 = oacc0 + sRed[64 + wrow * 16 + gid];
        float om8 = oacc8 + sRed[64 + wrow * 16 + gid + 8];
        const float geo = 1.0f / (1.0f - BETA_C);   // beta^512 underflows
        out[bBase + r0] = racc0 * ALPHA_C + om0 + bout * geo;
        out[bBase + r8] = racc8 * ALPHA_C + om8 + bout * geo;
    }
}

extern "C" void kernel_launch(void* const* d_in, const int* in_sizes, int n_in,
                              void* d_out, int out_size) {
    const float* input = (const float*)d_in[0];
    const float* W_rec = (const float*)d_in[1];
    const float* b_rec = (const float*)d_in[2];
    const float* W_out = (const float*)d_in[3];
    const float* b_out = (const float*)d_in[4];
    float* out = (float*)d_out;

    const size_t smem_bytes = SB_BYTES + SX_BYTES + NNT * 4 * 8 + 128 * 4; // ~107 KB
    cudaFuncSetAttribute(rnn_kernel, cudaFuncAttributeMaxDynamicSharedMemorySize,
                         (int)smem_bytes);

    rnn_kernel<<<B_TOTAL / BM, NTHREADS, smem_bytes>>>(input, W_rec, b_rec,
                                                       W_out, b_out, out);
    (void)in_sizes; (void)n_in; (void)out_size;
}

// round 13
// speedup vs baseline: 1.4406x; 1.4406x over previous
#include <cuda_runtime.h>
#include <cuda_fp16.h>
#include <cstdint>

#define B_TOTAL  8192
#define T_STEPS  512
#define HID      128
#define BM       64      // rows per CTA = 4 warps x 16-row M-tiles
#define NTHREADS 128
#define NKT      9       // k-tiles: 128 h + [x0,x1,bias,0..] tile
#define NNT      16      // main n-tiles: N = 128
#define ALPHA_C  0.2f
#define BETA_C   0.7f

#define SB_BYTES  (NKT * NNT * 32 * 16)   // 73728: fused uint4 per (nt,kt,lane)
#define SBW_BYTES (NKT * 32 * 8)          // 2304: W_out tile, uint2 per (kt,lane)

__device__ __forceinline__ uint32_t f16x2(float lo, float hi) {
    uint32_t r; asm("cvt.rn.f16x2.f32 %0, %1, %2;" : "=r"(r) : "f"(hi), "f"(lo));
    return r;
}
__device__ __forceinline__ uint32_t tanh2_hw(uint32_t p) {
    uint32_t r; asm("tanh.approx.f16x2 %0, %1;" : "=r"(r) : "r"(p)); return r;
}
__device__ __forceinline__ void mma16816(float c[4], const uint32_t a[4],
                                         uint32_t b0, uint32_t b1) {
    asm("mma.sync.aligned.m16n8k16.row.col.f32.f16.f16.f32 "
        "{%0,%1,%2,%3}, {%4,%5,%6,%7}, {%8,%9}, {%0,%1,%2,%3};"
        : "+f"(c[0]), "+f"(c[1]), "+f"(c[2]), "+f"(c[3])
        : "r"(a[0]), "r"(a[1]), "r"(a[2]), "r"(a[3]), "r"(b0), "r"(b1));
}

extern __shared__ char smem[];

__global__ __launch_bounds__(NTHREADS, 1)
void rnn_kernel(const float* __restrict__ input,   // (B, T, 2)
                const float* __restrict__ W_rec,   // (130, 128)
                const float* __restrict__ b_rec,   // (128)
                const float* __restrict__ W_out,   // (128, 1)
                const float* __restrict__ b_out,   // (1)
                float* __restrict__ out)           // (B)
{
    uint4*  sB  = (uint4*)smem;                          // [nt][kt][lane]
    uint2*  sBW = (uint2*)(smem + SB_BYTES);             // [kt][lane] W_out tile
    float2* sWP = (float2*)(smem + SB_BYTES + SBW_BYTES);// [nt][tig] wout pairs

    const int tid  = threadIdx.x;
    const int lane = tid & 31;
    const int wid  = tid >> 5;
    const int tig  = lane & 3;     // col group within fragment
    const int gid  = lane >> 2;    // row group 0..7
    const int bBase = blockIdx.x * BM;

    // ---- main B fragments: W'(k,n) split into f16 hi + residual, fused uint4
    // W'(k,n): k<128 -> W_rec[k+2][n]; 128->W_rec[0][n]; 129->W_rec[1][n];
    //          130 -> b_rec[n]; else 0.
    for (int idx = tid; idx < NKT * NNT * 32; idx += NTHREADS) {
        int l  = idx & 31;
        int kt = (idx >> 5) % NKT;
        int nt = (idx >> 5) / NKT;
        int n  = nt * 8 + (l >> 2);
        int kb = kt * 16 + 2 * (l & 3);
        unsigned short h0q[4], h1q[4];
        #pragma unroll
        for (int q = 0; q < 4; q++) {
            int k = kb + (q >> 1) * 8 + (q & 1);
            float v;
            if      (k < 128)  v = W_rec[(k + 2) * HID + n];
            else if (k == 128) v = W_rec[n];
            else if (k == 129) v = W_rec[HID + n];
            else if (k == 130) v = b_rec[n];
            else               v = 0.0f;
            __half vh = __float2half_rn(v);
            __half vl = __float2half_rn(v - __half2float(vh));
            h0q[q] = __half_as_ushort(vh);
            h1q[q] = __half_as_ushort(vl);
        }
        uint4 bv;
        bv.x = (uint32_t)h0q[0] | ((uint32_t)h0q[1] << 16);
        bv.y = (uint32_t)h0q[2] | ((uint32_t)h0q[3] << 16);
        bv.z = (uint32_t)h1q[0] | ((uint32_t)h1q[1] << 16);
        bv.w = (uint32_t)h1q[2] | ((uint32_t)h1q[3] << 16);
        sB[(nt * NKT + kt) * 32 + l] = bv;
    }
    // ---- omega tile: col 0 = f16(W_out) hi, col 1 = residual, cols 2..7 = 0;
    //      k >= 128 rows (x/bias) = 0.
    for (int idx = tid; idx < NKT * 32; idx += NTHREADS) {
        int l  = idx & 31;
        int kt = idx >> 5;
        int nl = l >> 2;
        int kb = kt * 16 + 2 * (l & 3);
        unsigned short hq[4];
        #pragma unroll
        for (int q = 0; q < 4; q++) {
            int k = kb + (q >> 1) * 8 + (q & 1);
            float v = 0.0f;
            if (k < 128 && nl < 2) {
                float w = W_out[k];
                __half wh = __float2half_rn(w);
                v = (nl == 0) ? __half2float(wh) : (w - __half2float(wh));
            }
            hq[q] = __half_as_ushort(__float2half_rn(v));
        }
        uint2 bw;
        bw.x = (uint32_t)hq[0] | ((uint32_t)hq[1] << 16);
        bw.y = (uint32_t)hq[2] | ((uint32_t)hq[3] << 16);
        sBW[kt * 32 + l] = bw;
    }
    if (tid < NNT * 4) {
        int nt = tid >> 2, c = tid & 3;
        sWP[tid] = make_float2(W_out[nt * 8 + 2 * c], W_out[nt * 8 + 2 * c + 1]);
    }
    __syncthreads();

    // ---- per-thread recurrent state ----
    const int r0 = wid * 16 + gid;     // local rows r0 and r0+8
    const int r8 = r0 + 8;
    const long long off0 = (long long)(bBase + r0) * (T_STEPS * 2);
    const long long off8 = (long long)(bBase + r8) * (T_STEPS * 2);
    const float bout = b_out[0];

    float2 x0c = *(const float2*)(input + off0);   // x_0
    float2 x8c = *(const float2*)(input + off8);
    float racc0 = 0.f, racc8 = 0.f, prev0 = 0.f, prev8 = 0.f;
    float oacc0 = 0.f, oacc8 = 0.f;    // sum of beta^() * (h_t . W_out), delayed

    const uint32_t ONEH = 0x00003C00u;   // {lo=1.0h (bias slot), hi=0}

    uint32_t a[NKT][4];
    #pragma unroll
    for (int kt = 0; kt < 8; kt++)
        #pragma unroll
        for (int q = 0; q < 4; q++) a[kt][q] = 0u;   // h_{-1} = 0
    a[8][0] = (tig == 0) ? f16x2(x0c.x, x0c.y) : (tig == 1) ? ONEH : 0u;
    a[8][1] = (tig == 0) ? f16x2(x8c.x, x8c.y) : (tig == 1) ? ONEH : 0u;
    a[8][2] = 0u; a[8][3] = 0u;

    for (int t = 0; t < T_STEPS; ++t) {
        float2 x0n = make_float2(0.f, 0.f), x8n = make_float2(0.f, 0.f);
        if (t + 1 < T_STEPS) {
            x0n = *(const float2*)(input + off0 + (long long)(t + 1) * 2);
            x8n = *(const float2*)(input + off8 + (long long)(t + 1) * 2);
        }

        float c[NNT][4];
        float cw[4];
        #pragma unroll
        for (int nt = 0; nt < NNT; nt++) {
            c[nt][0] = 0.f; c[nt][1] = 0.f; c[nt][2] = 0.f; c[nt][3] = 0.f;
        }
        cw[0] = 0.f; cw[1] = 0.f; cw[2] = 0.f; cw[3] = 0.f;

        // GEMM kt-outer: 16 independent c-tile chains + omega tile
        #pragma unroll
        for (int kt = 0; kt < NKT; kt++) {
            uint4 bv[NNT];
            const uint4* bp = sB + kt * 32 + lane;
            #pragma unroll
            for (int nt = 0; nt < NNT; nt++) bv[nt] = bp[nt * (NKT * 32)];
            uint2 bw = sBW[kt * 32 + lane];
            #pragma unroll
            for (int nt = 0; nt < NNT; nt++)
                mma16816(c[nt], a[kt], bv[nt].x, bv[nt].y);   // W hi
            mma16816(cw, a[kt], bw.x, bw.y);                  // omega (W_out)
            #pragma unroll
            for (int nt = 0; nt < NNT; nt++)
                mma16816(c[nt], a[kt], bv[nt].z, bv[nt].w);   // W residual
        }

        // epilogue: pack -> packed tanh -> directly next-step A fragments
        #pragma unroll
        for (int nt = 0; nt < NNT; nt++) {
            const int kt = nt >> 1, hh = (nt & 1) << 1;
            a[kt][hh]     = tanh2_hw(f16x2(c[nt][0], c[nt][1]));
            a[kt][hh + 1] = tanh2_hw(f16x2(c[nt][2], c[nt][3]));
        }
        // omega recursion (cw = h_{t-1}.W_out; zero on tig!=0 lanes)
        oacc0 = oacc0 * BETA_C + (cw[0] + cw[1]);
        oacc8 = oacc8 * BETA_C + (cw[2] + cw[3]);
        racc0 = racc0 * BETA_C + prev0 * prev0;  prev0 = x0c.x;
        racc8 = racc8 * BETA_C + prev8 * prev8;  prev8 = x8c.x;

        a[8][0] = (tig == 0) ? f16x2(x0n.x, x0n.y) : (tig == 1) ? ONEH : 0u;
        a[8][1] = (tig == 0) ? f16x2(x8n.x, x8n.y) : (tig == 1) ? ONEH : 0u;
        x0c = x0n; x8c = x8n;
    }

    // ---- final pr_511 = h_511 . W_out from resident A fragments (fp32) ----
    float pr0 = 0.f, pr8 = 0.f;
    #pragma unroll
    for (int nt = 0; nt < NNT; nt++) {
        const int kt = nt >> 1, hh = (nt & 1) << 1;
        float2 f0 = __half22float2(*(__half2*)&a[kt][hh]);
        float2 f8 = __half22float2(*(__half2*)&a[kt][hh + 1]);
        float2 wp = sWP[nt * 4 + tig];
        pr0 += f0.x * wp.x + f0.y * wp.y;
        pr8 += f8.x * wp.x + f8.y * wp.y;
    }
    pr0 += __shfl_xor_sync(0xffffffffu, pr0, 1);
    pr0 += __shfl_xor_sync(0xffffffffu, pr0, 2);
    pr8 += __shfl_xor_sync(0xffffffffu, pr8, 1);
    pr8 += __shfl_xor_sync(0xffffffffu, pr8, 2);

    if (tig == 0) {
        const float geo = 1.0f / (1.0f - BETA_C);   // beta^512 underflows
        out[bBase + r0] = racc0 * ALPHA_C + oacc0 * BETA_C + pr0 + bout * geo;
        out[bBase + r8] = racc8 * ALPHA_C + oacc8 * BETA_C + pr8 + bout * geo;
    }
}

extern "C" void kernel_launch(void* const* d_in, const int* in_sizes, int n_in,
                              void* d_out, int out_size) {
    const float* input = (const float*)d_in[0];
    const float* W_rec = (const float*)d_in[1];
    const float* b_rec = (const float*)d_in[2];
    const float* W_out = (const float*)d_in[3];
    const float* b_out = (const float*)d_in[4];
    float* out = (float*)d_out;

    const size_t smem_bytes = SB_BYTES + SBW_BYTES + NNT * 4 * sizeof(float2);
    cudaFuncSetAttribute(rnn_kernel, cudaFuncAttributeMaxDynamicSharedMemorySize,
                         (int)smem_bytes);

    rnn_kernel<<<B_TOTAL / BM, NTHREADS, smem_bytes>>>(input, W_rec, b_rec,
                                                       W_out, b_out, out);
    (void)in_sizes; (void)n_in; (void)out_size;
}

// round 14
// speedup vs baseline: 1.5295x; 1.0617x over previous
#include <cuda_runtime.h>
#include <cuda_fp16.h>
#include <cstdint>

#define B_TOTAL  8192
#define T_STEPS  512
#define HID      128
#define BM       64      // rows per CTA = 4 warps x 16-row M-tiles
#define NTHREADS 128
#define NKT      9       // k-tiles: 128 h + [x0,x1,bias,0..] tile
#define NNT      16      // n-tiles: N = 128
#define ALPHA_C  0.2f
#define BETA_C   0.7f

// B fragments: one uint4 per (nt,kt,lane) = {term0.b0, term0.b1, term1.b0, term1.b1}
#define SB_BYTES (NKT * NNT * 32 * 16)   // 73728

__device__ __forceinline__ float tanh_hw(float x) {
    float y; asm("tanh.approx.f32 %0, %1;" : "=f"(y) : "f"(x)); return y;
}
__device__ __forceinline__ uint32_t f16x2(float lo, float hi) {
    uint32_t r; asm("cvt.rn.f16x2.f32 %0, %1, %2;" : "=r"(r) : "f"(hi), "f"(lo));
    return r;
}
__device__ __forceinline__ void mma16816(float c[4], const uint32_t a[4],
                                         uint32_t b0, uint32_t b1) {
    asm("mma.sync.aligned.m16n8k16.row.col.f32.f16.f16.f32 "
        "{%0,%1,%2,%3}, {%4,%5,%6,%7}, {%8,%9}, {%0,%1,%2,%3};"
        : "+f"(c[0]), "+f"(c[1]), "+f"(c[2]), "+f"(c[3])
        : "r"(a[0]), "r"(a[1]), "r"(a[2]), "r"(a[3]), "r"(b0), "r"(b1));
}

extern __shared__ char smem[];

__global__ __launch_bounds__(NTHREADS, 1)
void rnn_kernel(const float* __restrict__ input,   // (B, T, 2)
                const float* __restrict__ W_rec,   // (130, 128)
                const float* __restrict__ b_rec,   // (128)
                const float* __restrict__ W_out,   // (128, 1)
                const float* __restrict__ b_out,   // (1)
                float* __restrict__ out)           // (B)
{
    uint4*  sB  = (uint4*)smem;                    // [nt][kt][lane]
    float2* sWP = (float2*)(smem + SB_BYTES);      // [nt][tig] wout col pairs

    const int tid  = threadIdx.x;
    const int lane = tid & 31;
    const int wid  = tid >> 5;
    const int tig  = lane & 3;     // col group within fragment
    const int gid  = lane >> 2;    // row group 0..7
    const int bBase = blockIdx.x * BM;

    // ---- build B fragments: W'(k,n) split into f16 hi (term0) + residual (term1)
    for (int idx = tid; idx < NKT * NNT * 32; idx += NTHREADS) {
        int l  = idx & 31;
        int kt = (idx >> 5) % NKT;
        int nt = (idx >> 5) / NKT;
        int n  = nt * 8 + (l >> 2);
        int kb = kt * 16 + 2 * (l & 3);
        unsigned short h0q[4], h1q[4];
        #pragma unroll
        for (int q = 0; q < 4; q++) {
            int k = kb + (q >> 1) * 8 + (q & 1);
            float v;
            if      (k < 128)  v = W_rec[(k + 2) * HID + n];
            else if (k == 128) v = W_rec[n];
            else if (k == 129) v = W_rec[HID + n];
            else if (k == 130) v = b_rec[n];
            else               v = 0.0f;
            __half vh = __float2half_rn(v);
            __half vl = __float2half_rn(v - __half2float(vh));
            h0q[q] = __half_as_ushort(vh);
            h1q[q] = __half_as_ushort(vl);
        }
        uint4 bv;
        bv.x = (uint32_t)h0q[0] | ((uint32_t)h0q[1] << 16);
        bv.y = (uint32_t)h0q[2] | ((uint32_t)h0q[3] << 16);
        bv.z = (uint32_t)h1q[0] | ((uint32_t)h1q[1] << 16);
        bv.w = (uint32_t)h1q[2] | ((uint32_t)h1q[3] << 16);
        sB[(nt * NKT + kt) * 32 + l] = bv;
    }
    if (tid < NNT * 4) {
        int nt = tid >> 2, c = tid & 3;
        sWP[tid] = make_float2(W_out[nt * 8 + 2 * c], W_out[nt * 8 + 2 * c + 1]);
    }
    __syncthreads();

    // ---- per-thread recurrent state ----
    const int r0 = wid * 16 + gid;     // local rows r0 and r0+8
    const int r8 = r0 + 8;
    const long long off0 = (long long)(bBase + r0) * (T_STEPS * 2);
    const long long off8 = (long long)(bBase + r8) * (T_STEPS * 2);
    const float bout = b_out[0];

    float2 x0c = *(const float2*)(input + off0);   // x_0
    float2 x8c = *(const float2*)(input + off8);
    float racc0 = 0.f, racc8 = 0.f, prev0 = 0.f, prev8 = 0.f;
    float oacc0 = 0.f, oacc8 = 0.f;

    const uint32_t ONEH = 0x00003C00u;   // {lo=1.0h (bias slot), hi=0}

    uint32_t a[NKT][4];
    #pragma unroll
    for (int kt = 0; kt < 8; kt++)
        #pragma unroll
        for (int q = 0; q < 4; q++) a[kt][q] = 0u;   // h_{-1} = 0
    a[8][0] = (tig == 0) ? f16x2(x0c.x, x0c.y) : (tig == 1) ? ONEH : 0u;
    a[8][1] = (tig == 0) ? f16x2(x8c.x, x8c.y) : (tig == 1) ? ONEH : 0u;
    a[8][2] = 0u; a[8][3] = 0u;

    for (int t = 0; t < T_STEPS; ++t) {
        float2 x0n = make_float2(0.f, 0.f), x8n = make_float2(0.f, 0.f);
        if (t + 1 < T_STEPS) {
            x0n = *(const float2*)(input + off0 + (long long)(t + 1) * 2);
            x8n = *(const float2*)(input + off8 + (long long)(t + 1) * 2);
        }

        float c[NNT][4];
        #pragma unroll
        for (int nt = 0; nt < NNT; nt++) {
            c[nt][0] = 0.f; c[nt][1] = 0.f; c[nt][2] = 0.f; c[nt][3] = 0.f;
        }

        // ---- phase 1: n-tiles 0..7, all k ----
        #pragma unroll
        for (int kt = 0; kt < NKT; kt++) {
            uint4 bv[8];
            const uint4* bp = sB + kt * 32 + lane;
            #pragma unroll
            for (int nt = 0; nt < 8; nt++) bv[nt] = bp[nt * (NKT * 32)];
            #pragma unroll
            for (int nt = 0; nt < 8; nt++)
                mma16816(c[nt], a[kt], bv[nt].x, bv[nt].y);   // W hi
            #pragma unroll
            for (int nt = 0; nt < 8; nt++)
                mma16816(c[nt], a[kt], bv[nt].z, bv[nt].w);   // W residual
        }

        // ---- phase 2: n-tiles 8..15, with tiles 0..7's epilogue interleaved
        //      (tanh/dot/pack run on MUFU/FMA pipes under the tensor stream).
        //      New fragments for kt 0..3 staged in an[] — a[0..3] still feed MMAs.
        uint32_t an[4][4];
        float pr0 = 0.f, pr8 = 0.f;
        #pragma unroll
        for (int kt = 0; kt < NKT; kt++) {
            uint4 bv[8];
            const uint4* bp = sB + (8 * NKT + kt) * 32 + lane;
            #pragma unroll
            for (int nt = 0; nt < 8; nt++) bv[nt] = bp[nt * (NKT * 32)];
            #pragma unroll
            for (int nt = 0; nt < 8; nt++)
                mma16816(c[8 + nt], a[kt], bv[nt].x, bv[nt].y);
            #pragma unroll
            for (int nt = 0; nt < 8; nt++)
                mma16816(c[8 + nt], a[kt], bv[nt].z, bv[nt].w);
            if (kt < 8) {
                const int nt = kt;              // epilogue of first-half tile
                float t0 = tanh_hw(c[nt][0]);
                float t1 = tanh_hw(c[nt][1]);
                float t2 = tanh_hw(c[nt][2]);
                float t3 = tanh_hw(c[nt][3]);
                float2 wp = sWP[nt * 4 + tig];
                pr0 += t0 * wp.x + t1 * wp.y;
                pr8 += t2 * wp.x + t3 * wp.y;
                const int kg = nt >> 1, hh = (nt & 1) << 1;
                an[kg][hh]     = f16x2(t0, t1);
                an[kg][hh + 1] = f16x2(t2, t3);
            }
        }

        // ---- second-half epilogue (a[4..7] no longer read) ----
        #pragma unroll
        for (int nt = 8; nt < NNT; nt++) {
            float t0 = tanh_hw(c[nt][0]);
            float t1 = tanh_hw(c[nt][1]);
            float t2 = tanh_hw(c[nt][2]);
            float t3 = tanh_hw(c[nt][3]);
            float2 wp = sWP[nt * 4 + tig];
            pr0 += t0 * wp.x + t1 * wp.y;
            pr8 += t2 * wp.x + t3 * wp.y;
            const int kg = nt >> 1, hh = (nt & 1) << 1;
            a[kg][hh]     = f16x2(t0, t1);
            a[kg][hh + 1] = f16x2(t2, t3);
        }
        // commit staged fragments for kt 0..3
        #pragma unroll
        for (int g = 0; g < 4; g++) {
            a[g][0] = an[g][0]; a[g][1] = an[g][1];
            a[g][2] = an[g][2]; a[g][3] = an[g][3];
        }

        oacc0 = oacc0 * BETA_C + pr0;
        oacc8 = oacc8 * BETA_C + pr8;
        racc0 = racc0 * BETA_C + prev0 * prev0;  prev0 = x0c.x;
        racc8 = racc8 * BETA_C + prev8 * prev8;  prev8 = x8c.x;

        a[8][0] = (tig == 0) ? f16x2(x0n.x, x0n.y) : (tig == 1) ? ONEH : 0u;
        a[8][1] = (tig == 0) ? f16x2(x8n.x, x8n.y) : (tig == 1) ? ONEH : 0u;
        x0c = x0n; x8c = x8n;
    }

    // reduce omega across the 4 col-group lanes of each quad
    oacc0 += __shfl_xor_sync(0xffffffffu, oacc0, 1);
    oacc0 += __shfl_xor_sync(0xffffffffu, oacc0, 2);
    oacc8 += __shfl_xor_sync(0xffffffffu, oacc8, 1);
    oacc8 += __shfl_xor_sync(0xffffffffu, oacc8, 2);

    if (tig == 0) {
        const float geo = 1.0f / (1.0f - BETA_C);   // beta^512 underflows
        out[bBase + r0] = racc0 * ALPHA_C + oacc0 + bout * geo;
        out[bBase + r8] = racc8 * ALPHA_C + oacc8 + bout * geo;
    }
}

extern "C" void kernel_launch(void* const* d_in, const int* in_sizes, int n_in,
                              void* d_out, int out_size) {
    const float* input = (const float*)d_in[0];
    const float* W_rec = (const float*)d_in[1];
    const float* b_rec = (const float*)d_in[2];
    const float* W_out = (const float*)d_in[3];
    const float* b_out = (const float*)d_in[4];
    float* out = (float*)d_out;

    const size_t smem_bytes = SB_BYTES + NNT * 4 * sizeof(float2);  // 74240
    cudaFuncSetAttribute(rnn_kernel, cudaFuncAttributeMaxDynamicSharedMemorySize,
                         (int)smem_bytes);

    rnn_kernel<<<B_TOTAL / BM, NTHREADS, smem_bytes>>>(input, W_rec, b_rec,
                                                       W_out, b_out, out);
    (void)in_sizes; (void)n_in; (void)out_size;
}

// round 15
// speedup vs baseline: 2.6336x; 1.7219x over previous
#include <cuda_runtime.h>
#include <cuda_fp16.h>
#include <cstdint>

#define B_TOTAL  8192
#define T_STEPS  512
#define HID      128
#define BM       64      // rows per CTA = 4 warps x 16-row M-tiles
#define NTHREADS 128
#define NKT      9       // k-tiles: 128 h + [x0,x1,bias,0..] tile
#define NNT      16      // n-tiles: N = 128
#define ALPHA_C  0.2f
#define BETA_C   0.7f

// B fragments (hi term only): one uint4 per (ntp,kt,lane) covering TWO n-tiles:
// {nt=2p.b0, nt=2p.b1, nt=2p+1.b0, nt=2p+1.b1}
#define SB_BYTES (8 * NKT * 32 * 16)   // 36864

__device__ __forceinline__ float tanh_hw(float x) {
    float y; asm("tanh.approx.f32 %0, %1;" : "=f"(y) : "f"(x)); return y;
}
__device__ __forceinline__ uint32_t f16x2(float lo, float hi) {
    uint32_t r; asm("cvt.rn.f16x2.f32 %0, %1, %2;" : "=r"(r) : "f"(hi), "f"(lo));
    return r;
}
__device__ __forceinline__ void mma16816(float c[4], const uint32_t a[4],
                                         uint32_t b0, uint32_t b1) {
    asm("mma.sync.aligned.m16n8k16.row.col.f32.f16.f16.f32 "
        "{%0,%1,%2,%3}, {%4,%5,%6,%7}, {%8,%9}, {%0,%1,%2,%3};"
        : "+f"(c[0]), "+f"(c[1]), "+f"(c[2]), "+f"(c[3])
        : "r"(a[0]), "r"(a[1]), "r"(a[2]), "r"(a[3]), "r"(b0), "r"(b1));
}

extern __shared__ char smem[];

__global__ __launch_bounds__(NTHREADS, 1)
void rnn_kernel(const float* __restrict__ input,   // (B, T, 2)
                const float* __restrict__ W_rec,   // (130, 128)
                const float* __restrict__ b_rec,   // (128)
                const float* __restrict__ W_out,   // (128, 1)
                const float* __restrict__ b_out,   // (1)
                float* __restrict__ out)           // (B)
{
    uint4*  sB  = (uint4*)smem;                    // [ntp][kt][lane]
    float2* sWP = (float2*)(smem + SB_BYTES);      // [nt][tig] wout col pairs

    const int tid  = threadIdx.x;
    const int lane = tid & 31;
    const int wid  = tid >> 5;
    const int tig  = lane & 3;     // col group within fragment
    const int gid  = lane >> 2;    // row group 0..7
    const int bBase = blockIdx.x * BM;

    // ---- build B fragments: W'(k,n) rounded to f16 (hi term only)
    // W'(k,n): k<128 -> W_rec[k+2][n]; 128->W_rec[0][n]; 129->W_rec[1][n];
    //          130 -> b_rec[n]; else 0.
    for (int idx = tid; idx < 8 * NKT * 32; idx += NTHREADS) {
        int l   = idx & 31;
        int kt  = (idx >> 5) % NKT;
        int ntp = (idx >> 5) / NKT;
        int kb  = kt * 16 + 2 * (l & 3);
        unsigned short hq[2][4];
        #pragma unroll
        for (int half = 0; half < 2; half++) {
            int n = (2 * ntp + half) * 8 + (l >> 2);
            #pragma unroll
            for (int q = 0; q < 4; q++) {
                int k = kb + (q >> 1) * 8 + (q & 1);
                float v;
                if      (k < 128)  v = W_rec[(k + 2) * HID + n];
                else if (k == 128) v = W_rec[n];
                else if (k == 129) v = W_rec[HID + n];
                else if (k == 130) v = b_rec[n];
                else               v = 0.0f;
                hq[half][q] = __half_as_ushort(__float2half_rn(v));
            }
        }
        uint4 bv;
        bv.x = (uint32_t)hq[0][0] | ((uint32_t)hq[0][1] << 16);
        bv.y = (uint32_t)hq[0][2] | ((uint32_t)hq[0][3] << 16);
        bv.z = (uint32_t)hq[1][0] | ((uint32_t)hq[1][1] << 16);
        bv.w = (uint32_t)hq[1][2] | ((uint32_t)hq[1][3] << 16);
        sB[(ntp * NKT + kt) * 32 + l] = bv;
    }
    if (tid < NNT * 4) {
        int nt = tid >> 2, c = tid & 3;
        sWP[tid] = make_float2(W_out[nt * 8 + 2 * c], W_out[nt * 8 + 2 * c + 1]);
    }
    __syncthreads();

    // ---- per-thread recurrent state ----
    const int r0 = wid * 16 + gid;     // local rows r0 and r0+8
    const int r8 = r0 + 8;
    const long long off0 = (long long)(bBase + r0) * (T_STEPS * 2);
    const long long off8 = (long long)(bBase + r8) * (T_STEPS * 2);
    const float bout = b_out[0];

    float2 x0c = *(const float2*)(input + off0);   // x_0
    float2 x8c = *(const float2*)(input + off8);
    float racc0 = 0.f, racc8 = 0.f, prev0 = 0.f, prev8 = 0.f;
    float oacc0 = 0.f, oacc8 = 0.f;

    const uint32_t ONEH = 0x00003C00u;   // {lo=1.0h (bias slot), hi=0}

    uint32_t a[NKT][4];
    #pragma unroll
    for (int kt = 0; kt < 8; kt++)
        #pragma unroll
        for (int q = 0; q < 4; q++) a[kt][q] = 0u;   // h_{-1} = 0
    a[8][0] = (tig == 0) ? f16x2(x0c.x, x0c.y) : (tig == 1) ? ONEH : 0u;
    a[8][1] = (tig == 0) ? f16x2(x8c.x, x8c.y) : (tig == 1) ? ONEH : 0u;
    a[8][2] = 0u; a[8][3] = 0u;

    for (int t = 0; t < T_STEPS; ++t) {
        float2 x0n = make_float2(0.f, 0.f), x8n = make_float2(0.f, 0.f);
        if (t + 1 < T_STEPS) {
            x0n = *(const float2*)(input + off0 + (long long)(t + 1) * 2);
            x8n = *(const float2*)(input + off8 + (long long)(t + 1) * 2);
        }

        float c[NNT][4];
        #pragma unroll
        for (int nt = 0; nt < NNT; nt++) {
            c[nt][0] = 0.f; c[nt][1] = 0.f; c[nt][2] = 0.f; c[nt][3] = 0.f;
        }

        // GEMM kt-outer: 8 fused loads (16 n-tiles) + 16 MMAs per kt
        #pragma unroll
        for (int kt = 0; kt < NKT; kt++) {
            uint4 bv[8];
            const uint4* bp = sB + kt * 32 + lane;
            #pragma unroll
            for (int p = 0; p < 8; p++) bv[p] = bp[p * (NKT * 32)];
            #pragma unroll
            for (int p = 0; p < 8; p++) {
                mma16816(c[2 * p],     a[kt], bv[p].x, bv[p].y);
                mma16816(c[2 * p + 1], a[kt], bv[p].z, bv[p].w);
            }
        }

        // epilogue: tanh -> omega partials -> repack D as next-step A fragments
        float pr0 = 0.f, pr8 = 0.f;
        #pragma unroll
        for (int nt = 0; nt < NNT; nt++) {
            float t0 = tanh_hw(c[nt][0]);
            float t1 = tanh_hw(c[nt][1]);
            float t2 = tanh_hw(c[nt][2]);
            float t3 = tanh_hw(c[nt][3]);
            float2 wp = sWP[nt * 4 + tig];
            pr0 += t0 * wp.x + t1 * wp.y;
            pr8 += t2 * wp.x + t3 * wp.y;
            const int kt = nt >> 1, hh = (nt & 1) << 1;
            a[kt][hh]     = f16x2(t0, t1);
            a[kt][hh + 1] = f16x2(t2, t3);
        }
        oacc0 = oacc0 * BETA_C + pr0;
        oacc8 = oacc8 * BETA_C + pr8;
        racc0 = racc0 * BETA_C + prev0 * prev0;  prev0 = x0c.x;
        racc8 = racc8 * BETA_C + prev8 * prev8;  prev8 = x8c.x;

        a[8][0] = (tig == 0) ? f16x2(x0n.x, x0n.y) : (tig == 1) ? ONEH : 0u;
        a[8][1] = (tig == 0) ? f16x2(x8n.x, x8n.y) : (tig == 1) ? ONEH : 0u;
        x0c = x0n; x8c = x8n;
    }

    // reduce omega across the 4 col-group lanes of each quad
    oacc0 += __shfl_xor_sync(0xffffffffu, oacc0, 1);
    oacc0 += __shfl_xor_sync(0xffffffffu, oacc0, 2);
    oacc8 += __shfl_xor_sync(0xffffffffu, oacc8, 1);
    oacc8 += __shfl_xor_sync(0xffffffffu, oacc8, 2);

    if (tig == 0) {
        const float geo = 1.0f / (1.0f - BETA_C);   // beta^512 underflows
        out[bBase + r0] = racc0 * ALPHA_C + oacc0 + bout * geo;
        out[bBase + r8] = racc8 * ALPHA_C + oacc8 + bout * geo;
    }
}

extern "C" void kernel_launch(void* const* d_in, const int* in_sizes, int n_in,
                              void* d_out, int out_size) {
    const float* input = (const float*)d_in[0];
    const float* W_rec = (const float*)d_in[1];
    const float* b_rec = (const float*)d_in[2];
    const float* W_out = (const float*)d_in[3];
    const float* b_out = (const float*)d_in[4];
    float* out = (float*)d_out;

    const size_t smem_bytes = SB_BYTES + NNT * 4 * sizeof(float2);  // 37376
    cudaFuncSetAttribute(rnn_kernel, cudaFuncAttributeMaxDynamicSharedMemorySize,
                         (int)smem_bytes);

    rnn_kernel<<<B_TOTAL / BM, NTHREADS, smem_bytes>>>(input, W_rec, b_rec,
                                                       W_out, b_out, out);
    (void)in_sizes; (void)n_in; (void)out_size;
}